// round 17
// baseline (speedup 1.0000x reference)
#include <cuda_runtime.h>

// S4D diagonal SSM scan — fused chunk-parallel kernel, real-only xs layout.
// B=4, D=128, N=64 complex states, L=1024.
// out = [ all_xs real parts (b,t,d,n): B*L*D*N | ys_real (b,d,t): B*D*L ].
// Conjugate symmetry (exact): x[n+32]=conj(x[n]) => row[i]=xr[i%32];
// y_t = sum_{n<32} 2*Cr_n*xr_n.
//
// One block (512 thr = 16 warps) per (b,d); warp c owns chunk [64c,64c+64).
// Phase 1: 4-step-blocked zero-seeded scan -> end state (u via one LDG.64).
// Phase 2: combine with dA^64. Phase 3: fully-unrolled seeded re-scan;
// u via one LDS.64 per 2 steps from smem; xs/y stores at constant offsets
// (no per-step pointer arithmetic); y via 16-step smem transpose reduce.

#define Dd 128
#define Nn 64
#define Bb 4
#define Ll 1024
#define CH 16
#define T0 64
#define ROWF (Dd * Nn)   // 8192 floats per timestep row

__global__ __launch_bounds__(512, 4) void s4d_fused_kernel(
    const float* __restrict__ us,          // (B, D, L)
    const float* __restrict__ log_dt,      // (D,)
    const float* __restrict__ log_A_real,  // (D, N/2)
    const float* __restrict__ A_imag,      // (D, N/2)
    const float* __restrict__ B_re,        // (D, N)
    const float* __restrict__ B_im,        // (D, N)
    const float* __restrict__ C_re,        // (D, N/2)
    float* __restrict__ out,
    size_t xs_floats, size_t out_floats)
{
    __shared__ float2 ends[CH][32];
    __shared__ float2 ubuf[CH][32];        // staged u chunk (float2 per lane)
    __shared__ float  ybuf[CH][32 * 17];   // [lane][step-in-group], pad 17

    const int lane = threadIdx.x & 31;     // state n = lane
    const int c    = threadIdx.x >> 5;     // chunk / warp id, 0..15
    const int d    = blockIdx.x & (Dd - 1);
    const int b    = blockIdx.x >> 7;

    // ---- bilinear discretization for state n = lane ----
    const float dt  = __expf(log_dt[d]);
    const float Are = -__expf(log_A_real[d * 32 + lane]);
    const float Aim = A_imag[d * 32 + lane];
    const float hr = 0.5f * dt * Are;
    const float hi = 0.5f * dt * Aim;
    const float den_r = 1.0f - hr;
    const float den_i = -hi;
    const float inv = 1.0f / (den_r * den_r + den_i * den_i);
    const float num_r = 1.0f + hr;
    const float dAr = (num_r * den_r + hi * den_i) * inv;
    const float dAi = (hi * den_r - num_r * den_i) * inv;
    const float tr = dt * B_re[d * 64 + lane];
    const float ti = dt * B_im[d * 64 + lane];
    const float dBr = (tr * den_r + ti * den_i) * inv;
    const float dBi = (ti * den_r - tr * den_i) * inv;
    const float Cr2 = 2.0f * C_re[d * 32 + lane];

    // one 64-float u chunk per warp as a single LDG.64; stage for phase 3
    const float2 upair = reinterpret_cast<const float2*>(
        us + (size_t)blockIdx.x * Ll + c * T0)[lane];
    ubuf[c][lane] = upair;

    // ---- Phase 1: 4-step-blocked zero-seeded chunk scan ----
    const float dA2r = dAr * dAr - dAi * dAi;
    const float dA2i = 2.0f * dAr * dAi;
    const float dA4r = dA2r * dA2r - dA2i * dA2i;
    const float dA4i = 2.0f * dA2r * dA2i;
    const float g3r = dAr * dBr - dAi * dBi;
    const float g3i = dAr * dBi + dAi * dBr;
    const float g2r = dA2r * dBr - dA2i * dBi;
    const float g2i = dA2r * dBi + dA2i * dBr;
    const float g1r = dA2r * g3r - dA2i * g3i;
    const float g1i = dA2r * g3i + dA2i * g3r;

    float xr = 0.f, xi = 0.f;
#pragma unroll
    for (int j = 0; j < 16; ++j) {
        // steps 4j..4j+3: u at lanes 2j, 2j+1 (x = even t, y = odd t)
        const float u1 = __shfl_sync(0xffffffffu, upair.x, 2 * j);
        const float u2 = __shfl_sync(0xffffffffu, upair.y, 2 * j);
        const float u3 = __shfl_sync(0xffffffffu, upair.x, 2 * j + 1);
        const float u4 = __shfl_sync(0xffffffffu, upair.y, 2 * j + 1);
        const float injr = fmaf(g1r, u1, fmaf(g2r, u2, fmaf(g3r, u3, dBr * u4)));
        const float inji = fmaf(g1i, u1, fmaf(g2i, u2, fmaf(g3i, u3, dBi * u4)));
        const float nr = fmaf(dA4r, xr, fmaf(-dA4i, xi, injr));
        const float ni = fmaf(dA4r, xi, fmaf( dA4i, xr, inji));
        xr = nr; xi = ni;
    }
    ends[c][lane] = make_float2(xr, xi);
    __syncthreads();

    // ---- Phase 2: init_c = sum_{j<c} (dA^64)^(c-1-j) * e_j ----
    {
        float pr = dA4r, pi = dA4i;         // dA^64 via 4 squarings
#pragma unroll
        for (int q = 0; q < 4; ++q) {
            const float sr = pr * pr - pi * pi;
            const float si = 2.0f * pr * pi;
            pr = sr; pi = si;
        }
        xr = 0.f; xi = 0.f;
        for (int j = 0; j < c; ++j) {
            const float2 e = ends[j][lane];
            const float nr = fmaf(pr, xr, fmaf(-pi, xi, e.x));
            const float ni = fmaf(pr, xi, fmaf( pi, xr, e.y));
            xr = nr; xi = ni;
        }
    }

    // ---- Phase 3: fully-unrolled seeded re-scan, emit xs + y ----
    const bool xs_ok = (xs_floats >= (size_t)Bb * Ll * Dd * Nn);
    const bool y_ok  = (out_floats >= xs_floats + (size_t)Bb * Dd * Ll);
    float* yb = ybuf[c];
    const float2* ub2 = ubuf[c];
    float* __restrict__ y_out =
        out + xs_floats + (size_t)blockIdx.x * Ll + c * T0;

    // base pointer for this lane's slot in row t = c*T0; all later stores
    // use compile-time-constant offsets from here.
    float* __restrict__ p0 =
        out + ((size_t)(b * Ll + c * T0) * Dd + d) * (size_t)Nn + lane;

#pragma unroll
    for (int g = 0; g < 4; ++g) {           // 4 groups of 16 steps
#pragma unroll
        for (int h = 0; h < 8; ++h) {       // 2 steps per iteration
            const float2 uu = ub2[g * 8 + h];   // one LDS.64 for both steps

            // even step: t-in-chunk = g*16 + 2h
            {
                const float nr = fmaf(dAr, xr, fmaf(-dAi, xi, dBr * uu.x));
                const float ni = fmaf(dAr, xi, fmaf( dAi, xr, dBi * uu.x));
                xr = nr; xi = ni;
                if (xs_ok) {
                    p0[(size_t)(g * 16 + 2 * h) * ROWF]      = xr;
                    p0[(size_t)(g * 16 + 2 * h) * ROWF + 32] = xr;
                }
                yb[lane * 17 + 2 * h] = Cr2 * xr;
            }
            // odd step: t-in-chunk = g*16 + 2h + 1
            {
                const float nr = fmaf(dAr, xr, fmaf(-dAi, xi, dBr * uu.y));
                const float ni = fmaf(dAr, xi, fmaf( dAi, xr, dBi * uu.y));
                xr = nr; xi = ni;
                if (xs_ok) {
                    p0[(size_t)(g * 16 + 2 * h + 1) * ROWF]      = xr;
                    p0[(size_t)(g * 16 + 2 * h + 1) * ROWF + 32] = xr;
                }
                yb[lane * 17 + 2 * h + 1] = Cr2 * xr;
            }
        }
        __syncwarp();
        // transposed reduce: lane pair (l, l+16) sums halves of column l&15
        float acc = 0.f;
        const int col = lane & 15;
        const int hb  = lane & 16;
#pragma unroll
        for (int i = 0; i < 16; ++i)
            acc += yb[(hb + i) * 17 + col];
        acc += __shfl_xor_sync(0xffffffffu, acc, 16);
        if (y_ok && lane < 16)
            y_out[g * 16 + lane] = acc;
        __syncwarp();
    }
}

extern "C" void kernel_launch(void* const* d_in, const int* in_sizes, int n_in,
                              void* d_out, int out_size)
{
    (void)in_sizes; (void)n_in;
    const float* us         = (const float*)d_in[0];
    const float* log_dt     = (const float*)d_in[1];
    const float* log_A_real = (const float*)d_in[2];
    const float* A_imag     = (const float*)d_in[3];
    const float* B_re       = (const float*)d_in[4];
    const float* B_im       = (const float*)d_in[5];
    const float* C_re       = (const float*)d_in[6];
    float* out = (float*)d_out;

    const size_t out_floats = (size_t)out_size;
    const size_t ys_floats  = (size_t)Bb * Dd * Ll;
    const size_t xs_floats  = (out_floats > ys_floats) ? (out_floats - ys_floats) : 0;

    s4d_fused_kernel<<<Bb * Dd, 512>>>(us, log_dt, log_A_real, A_imag,
                                       B_re, B_im, C_re, out,
                                       xs_floats, out_floats);
}